// round 1
// baseline (speedup 1.0000x reference)
#include <cuda_runtime.h>
#include <cuda_bf16.h>
#include <math.h>

// ---------------------------------------------------------------------------
// ViT attention, fp32 SIMT baseline.
// B=4, S=2048, E=768, H=12, D=64.
// Outputs (concatenated in d_out): attn_output [4,2048,768] then
// attn_weights [4,12,2048,2048].
// ---------------------------------------------------------------------------

#define BATCH     4
#define SEQ       2048
#define EMB       768
#define HEADS     12
#define HDIM      64
#define MTOK      (BATCH * SEQ)          // 8192
#define SCALE_F   0.125f                  // 64^-0.5

// Scratch (device globals — no allocation allowed)
__device__ float g_q[MTOK * EMB];
__device__ float g_k[MTOK * EMB];
__device__ float g_v[MTOK * EMB];
__device__ float g_att[MTOK * EMB];

// ---------------------------------------------------------------------------
// C[M,N] = A[M,K] @ W[N,K]^T + bias   (torch Linear)
// Tiles: 64x64, K-chunk 16. 256 threads, 4x4 micro-tile per thread.
// ---------------------------------------------------------------------------
__global__ void gemm_xwT_kernel(const float* __restrict__ A,
                                const float* __restrict__ W,
                                const float* __restrict__ bias,
                                float* __restrict__ C,
                                int M, int N, int K) {
    __shared__ float As[64][17];
    __shared__ float Bs[64][17];

    const int m0 = blockIdx.y * 64;
    const int n0 = blockIdx.x * 64;
    const int tid = threadIdx.x;
    const int tx = tid & 15;        // 0..15 -> 4 output cols each
    const int ty = tid >> 4;        // 0..15 -> 4 output rows each

    float acc[4][4] = {};

    for (int k0 = 0; k0 < K; k0 += 16) {
        #pragma unroll
        for (int i = 0; i < 4; i++) {
            int idx = tid + i * 256;       // 0..1023
            int r = idx >> 4;
            int c = idx & 15;
            As[r][c] = A[(size_t)(m0 + r) * K + k0 + c];
            Bs[r][c] = W[(size_t)(n0 + r) * K + k0 + c];
        }
        __syncthreads();

        #pragma unroll
        for (int kk = 0; kk < 16; kk++) {
            float a[4], b[4];
            #pragma unroll
            for (int i = 0; i < 4; i++) a[i] = As[ty * 4 + i][kk];
            #pragma unroll
            for (int j = 0; j < 4; j++) b[j] = Bs[tx * 4 + j][kk];
            #pragma unroll
            for (int i = 0; i < 4; i++)
                #pragma unroll
                for (int j = 0; j < 4; j++)
                    acc[i][j] += a[i] * b[j];
        }
        __syncthreads();
    }

    #pragma unroll
    for (int i = 0; i < 4; i++) {
        int m = m0 + ty * 4 + i;
        #pragma unroll
        for (int j = 0; j < 4; j++) {
            int n = n0 + tx * 4 + j;
            C[(size_t)m * N + n] = acc[i][j] + bias[n];
        }
    }
}

// ---------------------------------------------------------------------------
// Scores: for each (b,h): S_tile = (Q_tile @ K_tile^T) * scale
// Q/K live in g_q/g_k with layout [b*S+s, h*64+d].
// Output: wbuf[bh*S*S + q*S + k]  (pre-softmax)
// Grid: (qtile=32, ktile=32, bh=48), 256 threads, 64x64 tile.
// ---------------------------------------------------------------------------
__global__ void scores_kernel(float* __restrict__ wbuf) {
    const int bh = blockIdx.z;
    const int b  = bh / HEADS;
    const int h  = bh % HEADS;
    const int q0 = blockIdx.x * 64;
    const int k0 = blockIdx.y * 64;
    const int tid = threadIdx.x;

    __shared__ float Qs[64][65];
    __shared__ float Ks[64][65];

    #pragma unroll
    for (int i = 0; i < 16; i++) {
        int idx = tid + i * 256;        // 0..4095
        int r = idx >> 6;
        int c = idx & 63;
        Qs[r][c] = g_q[(size_t)(b * SEQ + q0 + r) * EMB + h * HDIM + c];
        Ks[r][c] = g_k[(size_t)(b * SEQ + k0 + r) * EMB + h * HDIM + c];
    }
    __syncthreads();

    const int tx = tid & 15;
    const int ty = tid >> 4;
    float acc[4][4] = {};

    #pragma unroll 8
    for (int kk = 0; kk < HDIM; kk++) {
        float a[4], bv[4];
        #pragma unroll
        for (int i = 0; i < 4; i++) a[i]  = Qs[ty * 4 + i][kk];
        #pragma unroll
        for (int j = 0; j < 4; j++) bv[j] = Ks[tx * 4 + j][kk];
        #pragma unroll
        for (int i = 0; i < 4; i++)
            #pragma unroll
            for (int j = 0; j < 4; j++)
                acc[i][j] += a[i] * bv[j];
    }

    const size_t base = (size_t)bh * SEQ * SEQ;
    #pragma unroll
    for (int i = 0; i < 4; i++) {
        int q = q0 + ty * 4 + i;
        #pragma unroll
        for (int j = 0; j < 4; j++) {
            int k = k0 + tx * 4 + j;
            wbuf[base + (size_t)q * SEQ + k] = acc[i][j] * SCALE_F;
        }
    }
}

// ---------------------------------------------------------------------------
// In-place row softmax over last dim (2048). One block (256 thr) per row.
// ---------------------------------------------------------------------------
__global__ void softmax_kernel(float* __restrict__ wbuf) {
    const size_t row = blockIdx.x;
    float* p = wbuf + row * (size_t)SEQ;
    const int tid = threadIdx.x;

    float v[8];
    float mx = -1e30f;
    #pragma unroll
    for (int i = 0; i < 8; i++) {
        v[i] = p[tid + i * 256];
        mx = fmaxf(mx, v[i]);
    }

    __shared__ float red[32];
    // warp max
    #pragma unroll
    for (int o = 16; o > 0; o >>= 1)
        mx = fmaxf(mx, __shfl_xor_sync(0xffffffffu, mx, o));
    if ((tid & 31) == 0) red[tid >> 5] = mx;
    __syncthreads();
    if (tid < 32) {
        float t = (tid < 8) ? red[tid] : -1e30f;
        #pragma unroll
        for (int o = 4; o > 0; o >>= 1)
            t = fmaxf(t, __shfl_xor_sync(0xffffffffu, t, o));
        red[tid] = t;
    }
    __syncthreads();
    mx = red[0];

    float s = 0.f;
    #pragma unroll
    for (int i = 0; i < 8; i++) {
        v[i] = __expf(v[i] - mx);
        s += v[i];
    }
    __syncthreads();
    // warp sum
    #pragma unroll
    for (int o = 16; o > 0; o >>= 1)
        s += __shfl_xor_sync(0xffffffffu, s, o);
    if ((tid & 31) == 0) red[tid >> 5] = s;
    __syncthreads();
    if (tid < 32) {
        float t = (tid < 8) ? red[tid] : 0.f;
        #pragma unroll
        for (int o = 4; o > 0; o >>= 1)
            t += __shfl_xor_sync(0xffffffffu, t, o);
        red[tid] = t;
    }
    __syncthreads();
    const float inv = 1.0f / red[0];

    #pragma unroll
    for (int i = 0; i < 8; i++)
        p[tid + i * 256] = v[i] * inv;
}

// ---------------------------------------------------------------------------
// PV: per (b,h):  O[2048,64] = W[2048,2048] @ V[2048,64]
// Output into g_att with layout [b*S+q, h*64+d].
// Grid: (mtile=32, 1, bh=48), 256 threads, 64x64 output tile, K-chunk 64.
// ---------------------------------------------------------------------------
__global__ void pv_kernel(const float* __restrict__ wbuf) {
    const int bh = blockIdx.z;
    const int b  = bh / HEADS;
    const int h  = bh % HEADS;
    const int m0 = blockIdx.x * 64;
    const int tid = threadIdx.x;

    __shared__ float Ws[64][65];
    __shared__ float Vs[64][65];

    const float* wrow = wbuf + (size_t)bh * SEQ * SEQ;

    const int tx = tid & 15;
    const int ty = tid >> 4;
    float acc[4][4] = {};

    for (int k0 = 0; k0 < SEQ; k0 += 64) {
        #pragma unroll
        for (int i = 0; i < 16; i++) {
            int idx = tid + i * 256;
            int r = idx >> 6;
            int c = idx & 63;
            Ws[r][c] = wrow[(size_t)(m0 + r) * SEQ + k0 + c];
            Vs[r][c] = g_v[(size_t)(b * SEQ + k0 + r) * EMB + h * HDIM + c];
        }
        __syncthreads();

        #pragma unroll 8
        for (int kk = 0; kk < 64; kk++) {
            float a[4], bv[4];
            #pragma unroll
            for (int i = 0; i < 4; i++) a[i]  = Ws[ty * 4 + i][kk];
            #pragma unroll
            for (int j = 0; j < 4; j++) bv[j] = Vs[kk][tx * 4 + j];
            #pragma unroll
            for (int i = 0; i < 4; i++)
                #pragma unroll
                for (int j = 0; j < 4; j++)
                    acc[i][j] += a[i] * bv[j];
        }
        __syncthreads();
    }

    #pragma unroll
    for (int i = 0; i < 4; i++) {
        int q = m0 + ty * 4 + i;
        #pragma unroll
        for (int j = 0; j < 4; j++) {
            int d = tx * 4 + j;
            g_att[(size_t)(b * SEQ + q) * EMB + h * HDIM + d] = acc[i][j];
        }
    }
}

// ---------------------------------------------------------------------------
// launch
// ---------------------------------------------------------------------------
extern "C" void kernel_launch(void* const* d_in, const int* in_sizes, int n_in,
                              void* d_out, int out_size) {
    (void)in_sizes; (void)n_in; (void)out_size;

    const float* hs = (const float*)d_in[0];
    const float* Wq = (const float*)d_in[1];
    const float* bq = (const float*)d_in[2];
    const float* Wk = (const float*)d_in[3];
    const float* bk = (const float*)d_in[4];
    const float* Wv = (const float*)d_in[5];
    const float* bv = (const float*)d_in[6];
    const float* Wo = (const float*)d_in[7];
    const float* bo = (const float*)d_in[8];

    float* out      = (float*)d_out;
    float* attn_out = out;                                    // [4,2048,768]
    float* wbuf     = out + (size_t)MTOK * EMB;               // [4,12,2048,2048]

    // device-global scratch addresses (resolved at launch via symbols)
    float* dq, * dk, * dv, * datt;
    cudaGetSymbolAddress((void**)&dq,   g_q);
    cudaGetSymbolAddress((void**)&dk,   g_k);
    cudaGetSymbolAddress((void**)&dv,   g_v);
    cudaGetSymbolAddress((void**)&datt, g_att);

    dim3 gproj(EMB / 64, MTOK / 64);   // (12, 128)

    // QKV projections
    gemm_xwT_kernel<<<gproj, 256>>>(hs, Wq, bq, dq, MTOK, EMB, EMB);
    gemm_xwT_kernel<<<gproj, 256>>>(hs, Wk, bk, dk, MTOK, EMB, EMB);
    gemm_xwT_kernel<<<gproj, 256>>>(hs, Wv, bv, dv, MTOK, EMB, EMB);

    // scores -> wbuf (pre-softmax)
    scores_kernel<<<dim3(SEQ / 64, SEQ / 64, BATCH * HEADS), 256>>>(wbuf);

    // softmax in place
    softmax_kernel<<<BATCH * HEADS * SEQ, 256>>>(wbuf);

    // PV -> g_att
    pv_kernel<<<dim3(SEQ / 64, 1, BATCH * HEADS), 256>>>(wbuf);

    // output projection
    gemm_xwT_kernel<<<gproj, 256>>>(datt, Wo, bo, attn_out, MTOK, EMB, EMB);
}

// round 2
// speedup vs baseline: 2.7341x; 2.7341x over previous
#include <cuda_runtime.h>
#include <cuda_bf16.h>
#include <math.h>
#include <stdint.h>

// ---------------------------------------------------------------------------
// ViT attention, TF32 tensor-core version (mma.sync.m16n8k8).
// B=4, S=2048, E=768, H=12, D=64.
// d_out = attn_output [4,2048,768] ++ attn_weights [4,12,2048,2048].
// ---------------------------------------------------------------------------

#define BATCH     4
#define SEQ       2048
#define EMB       768
#define HEADS     12
#define HDIM      64
#define MTOK      (BATCH * SEQ)          // 8192
#define SCALE_F   0.125f

#define PAD       36                     // smem row stride (floats): 4*g+t banks
#define VPAD      72                     // V tile row stride: 8*t+g banks

// Scratch (device globals — no allocation allowed)
__device__ float g_q[MTOK * EMB];
__device__ float g_k[MTOK * EMB];
__device__ float g_v[MTOK * EMB];
__device__ float g_att[MTOK * EMB];

__device__ __forceinline__ float to_tf32(float x) {
    float r;
    asm("cvt.rna.tf32.f32 %0, %1;" : "=f"(r) : "f"(x));
    return r;
}

__device__ __forceinline__ void mma_tf32(float c[4],
                                         uint32_t a0, uint32_t a1, uint32_t a2, uint32_t a3,
                                         uint32_t b0, uint32_t b1) {
    asm volatile(
        "mma.sync.aligned.m16n8k8.row.col.f32.tf32.tf32.f32 "
        "{%0,%1,%2,%3}, {%4,%5,%6,%7}, {%8,%9}, {%0,%1,%2,%3};\n"
        : "+f"(c[0]), "+f"(c[1]), "+f"(c[2]), "+f"(c[3])
        : "r"(a0), "r"(a1), "r"(a2), "r"(a3), "r"(b0), "r"(b1));
}

// ---------------------------------------------------------------------------
// C[M,N] = A[M,K] @ W[N,K]^T + bias.  Block tile 128x64, 8 warps (4m x 2n),
// warp tile 32x32 (2x4 mma of m16n8k8). K-chunk 32.
// grid: (N/64, M/128), 256 threads.
// ---------------------------------------------------------------------------
__global__ void gemm_xwT_tc(const float* __restrict__ A,
                            const float* __restrict__ W,
                            const float* __restrict__ bias,
                            float* __restrict__ C,
                            int M, int N, int K) {
    __shared__ float As[128][PAD];
    __shared__ float Ws[64][PAD];

    const int m0 = blockIdx.y * 128;
    const int n0 = blockIdx.x * 64;
    const int tid = threadIdx.x;
    const int wid = tid >> 5;
    const int lane = tid & 31;
    const int wm = (wid >> 1) * 32;
    const int wn = (wid & 1) * 32;
    const int g = lane >> 2;
    const int t = lane & 3;

    float acc[2][4][4] = {};

    for (int k0 = 0; k0 < K; k0 += 32) {
        // A tile: 128x32 = 1024 float4
        #pragma unroll
        for (int i = 0; i < 4; i++) {
            int idx = tid + i * 256;
            int r = idx >> 3, c4 = idx & 7;
            float4 v = *(const float4*)&A[(size_t)(m0 + r) * K + k0 + c4 * 4];
            As[r][c4 * 4 + 0] = to_tf32(v.x);
            As[r][c4 * 4 + 1] = to_tf32(v.y);
            As[r][c4 * 4 + 2] = to_tf32(v.z);
            As[r][c4 * 4 + 3] = to_tf32(v.w);
        }
        // W tile: 64x32 = 512 float4
        #pragma unroll
        for (int i = 0; i < 2; i++) {
            int idx = tid + i * 256;
            int r = idx >> 3, c4 = idx & 7;
            float4 v = *(const float4*)&W[(size_t)(n0 + r) * K + k0 + c4 * 4];
            Ws[r][c4 * 4 + 0] = to_tf32(v.x);
            Ws[r][c4 * 4 + 1] = to_tf32(v.y);
            Ws[r][c4 * 4 + 2] = to_tf32(v.z);
            Ws[r][c4 * 4 + 3] = to_tf32(v.w);
        }
        __syncthreads();

        #pragma unroll
        for (int kk = 0; kk < 4; kk++) {
            const int kb = kk * 8;
            uint32_t a[2][4], b[4][2];
            #pragma unroll
            for (int mi = 0; mi < 2; mi++) {
                int row = wm + mi * 16;
                a[mi][0] = __float_as_uint(As[row + g][kb + t]);
                a[mi][1] = __float_as_uint(As[row + 8 + g][kb + t]);
                a[mi][2] = __float_as_uint(As[row + g][kb + 4 + t]);
                a[mi][3] = __float_as_uint(As[row + 8 + g][kb + 4 + t]);
            }
            #pragma unroll
            for (int ni = 0; ni < 4; ni++) {
                int col = wn + ni * 8;
                b[ni][0] = __float_as_uint(Ws[col + g][kb + t]);
                b[ni][1] = __float_as_uint(Ws[col + g][kb + 4 + t]);
            }
            #pragma unroll
            for (int mi = 0; mi < 2; mi++)
                #pragma unroll
                for (int ni = 0; ni < 4; ni++)
                    mma_tf32(acc[mi][ni], a[mi][0], a[mi][1], a[mi][2], a[mi][3],
                             b[ni][0], b[ni][1]);
        }
        __syncthreads();
    }

    #pragma unroll
    for (int mi = 0; mi < 2; mi++) {
        #pragma unroll
        for (int ni = 0; ni < 4; ni++) {
            int m = m0 + wm + mi * 16 + g;
            int n = n0 + wn + ni * 8 + t * 2;
            C[(size_t)m * N + n]           = acc[mi][ni][0] + bias[n];
            C[(size_t)m * N + n + 1]       = acc[mi][ni][1] + bias[n + 1];
            C[(size_t)(m + 8) * N + n]     = acc[mi][ni][2] + bias[n];
            C[(size_t)(m + 8) * N + n + 1] = acc[mi][ni][3] + bias[n + 1];
        }
    }
}

// ---------------------------------------------------------------------------
// Scores: per (b,h): S = (Q @ K^T) * scale into wbuf (pre-softmax).
// Block tile 128(q) x 64(k), K-dim = HDIM = 64 (2 chunks of 32).
// grid: (SEQ/64, SEQ/128, B*H), 256 threads.
// ---------------------------------------------------------------------------
__global__ void scores_tc(float* __restrict__ wbuf) {
    __shared__ float Qs[128][PAD];
    __shared__ float Ks[64][PAD];

    const int bh = blockIdx.z;
    const int b  = bh / HEADS;
    const int h  = bh % HEADS;
    const int m0 = blockIdx.y * 128;
    const int n0 = blockIdx.x * 64;
    const int tid = threadIdx.x;
    const int wid = tid >> 5;
    const int lane = tid & 31;
    const int wm = (wid >> 1) * 32;
    const int wn = (wid & 1) * 32;
    const int g = lane >> 2;
    const int t = lane & 3;

    float acc[2][4][4] = {};

    #pragma unroll
    for (int k0 = 0; k0 < HDIM; k0 += 32) {
        #pragma unroll
        for (int i = 0; i < 4; i++) {
            int idx = tid + i * 256;
            int r = idx >> 3, c4 = idx & 7;
            float4 v = *(const float4*)&g_q[(size_t)(b * SEQ + m0 + r) * EMB + h * HDIM + k0 + c4 * 4];
            Qs[r][c4 * 4 + 0] = to_tf32(v.x);
            Qs[r][c4 * 4 + 1] = to_tf32(v.y);
            Qs[r][c4 * 4 + 2] = to_tf32(v.z);
            Qs[r][c4 * 4 + 3] = to_tf32(v.w);
        }
        #pragma unroll
        for (int i = 0; i < 2; i++) {
            int idx = tid + i * 256;
            int r = idx >> 3, c4 = idx & 7;
            float4 v = *(const float4*)&g_k[(size_t)(b * SEQ + n0 + r) * EMB + h * HDIM + k0 + c4 * 4];
            Ks[r][c4 * 4 + 0] = to_tf32(v.x);
            Ks[r][c4 * 4 + 1] = to_tf32(v.y);
            Ks[r][c4 * 4 + 2] = to_tf32(v.z);
            Ks[r][c4 * 4 + 3] = to_tf32(v.w);
        }
        __syncthreads();

        #pragma unroll
        for (int kk = 0; kk < 4; kk++) {
            const int kb = kk * 8;
            uint32_t a[2][4], bb[4][2];
            #pragma unroll
            for (int mi = 0; mi < 2; mi++) {
                int row = wm + mi * 16;
                a[mi][0] = __float_as_uint(Qs[row + g][kb + t]);
                a[mi][1] = __float_as_uint(Qs[row + 8 + g][kb + t]);
                a[mi][2] = __float_as_uint(Qs[row + g][kb + 4 + t]);
                a[mi][3] = __float_as_uint(Qs[row + 8 + g][kb + 4 + t]);
            }
            #pragma unroll
            for (int ni = 0; ni < 4; ni++) {
                int col = wn + ni * 8;
                bb[ni][0] = __float_as_uint(Ks[col + g][kb + t]);
                bb[ni][1] = __float_as_uint(Ks[col + g][kb + 4 + t]);
            }
            #pragma unroll
            for (int mi = 0; mi < 2; mi++)
                #pragma unroll
                for (int ni = 0; ni < 4; ni++)
                    mma_tf32(acc[mi][ni], a[mi][0], a[mi][1], a[mi][2], a[mi][3],
                             bb[ni][0], bb[ni][1]);
        }
        __syncthreads();
    }

    const size_t base = (size_t)bh * SEQ * SEQ;
    #pragma unroll
    for (int mi = 0; mi < 2; mi++) {
        #pragma unroll
        for (int ni = 0; ni < 4; ni++) {
            int m = m0 + wm + mi * 16 + g;
            int n = n0 + wn + ni * 8 + t * 2;
            wbuf[base + (size_t)m * SEQ + n]           = acc[mi][ni][0] * SCALE_F;
            wbuf[base + (size_t)m * SEQ + n + 1]       = acc[mi][ni][1] * SCALE_F;
            wbuf[base + (size_t)(m + 8) * SEQ + n]     = acc[mi][ni][2] * SCALE_F;
            wbuf[base + (size_t)(m + 8) * SEQ + n + 1] = acc[mi][ni][3] * SCALE_F;
        }
    }
}

// ---------------------------------------------------------------------------
// In-place row softmax over last dim (2048). One block (256 thr) per row.
// ---------------------------------------------------------------------------
__global__ void softmax_kernel(float* __restrict__ wbuf) {
    const size_t row = blockIdx.x;
    float* p = wbuf + row * (size_t)SEQ;
    const int tid = threadIdx.x;

    float v[8];
    float mx = -1e30f;
    #pragma unroll
    for (int i = 0; i < 8; i++) {
        v[i] = p[tid + i * 256];
        mx = fmaxf(mx, v[i]);
    }

    __shared__ float red[32];
    #pragma unroll
    for (int o = 16; o > 0; o >>= 1)
        mx = fmaxf(mx, __shfl_xor_sync(0xffffffffu, mx, o));
    if ((tid & 31) == 0) red[tid >> 5] = mx;
    __syncthreads();
    if (tid < 32) {
        float tt = (tid < 8) ? red[tid] : -1e30f;
        #pragma unroll
        for (int o = 4; o > 0; o >>= 1)
            tt = fmaxf(tt, __shfl_xor_sync(0xffffffffu, tt, o));
        red[tid] = tt;
    }
    __syncthreads();
    mx = red[0];

    float s = 0.f;
    #pragma unroll
    for (int i = 0; i < 8; i++) {
        v[i] = __expf(v[i] - mx);
        s += v[i];
    }
    __syncthreads();
    #pragma unroll
    for (int o = 16; o > 0; o >>= 1)
        s += __shfl_xor_sync(0xffffffffu, s, o);
    if ((tid & 31) == 0) red[tid >> 5] = s;
    __syncthreads();
    if (tid < 32) {
        float tt = (tid < 8) ? red[tid] : 0.f;
        #pragma unroll
        for (int o = 4; o > 0; o >>= 1)
            tt += __shfl_xor_sync(0xffffffffu, tt, o);
        red[tid] = tt;
    }
    __syncthreads();
    const float inv = 1.0f / red[0];

    #pragma unroll
    for (int i = 0; i < 8; i++)
        p[tid + i * 256] = v[i] * inv;
}

// ---------------------------------------------------------------------------
// PV: per (b,h): O[2048,64] = P[2048,2048] @ V[2048,64] -> g_att.
// Block tile 128(m) x 64(n), K-chunk 32 over 2048.
// grid: (1, SEQ/128, B*H), 256 threads.
// ---------------------------------------------------------------------------
__global__ void pv_tc(const float* __restrict__ wbuf) {
    __shared__ float Ps[128][PAD];   // [m][k]
    __shared__ float Vs[32][VPAD];   // [k][n]

    const int bh = blockIdx.z;
    const int b  = bh / HEADS;
    const int h  = bh % HEADS;
    const int m0 = blockIdx.y * 128;
    const int tid = threadIdx.x;
    const int wid = tid >> 5;
    const int lane = tid & 31;
    const int wm = (wid >> 1) * 32;
    const int wn = (wid & 1) * 32;
    const int g = lane >> 2;
    const int t = lane & 3;

    const float* prow = wbuf + (size_t)bh * SEQ * SEQ;
    float acc[2][4][4] = {};

    for (int k0 = 0; k0 < SEQ; k0 += 32) {
        #pragma unroll
        for (int i = 0; i < 4; i++) {
            int idx = tid + i * 256;
            int r = idx >> 3, c4 = idx & 7;
            float4 v = *(const float4*)&prow[(size_t)(m0 + r) * SEQ + k0 + c4 * 4];
            Ps[r][c4 * 4 + 0] = to_tf32(v.x);
            Ps[r][c4 * 4 + 1] = to_tf32(v.y);
            Ps[r][c4 * 4 + 2] = to_tf32(v.z);
            Ps[r][c4 * 4 + 3] = to_tf32(v.w);
        }
        // V tile: 32 rows (k) x 64 cols (n) = 512 float4
        #pragma unroll
        for (int i = 0; i < 2; i++) {
            int idx = tid + i * 256;
            int r = idx >> 4, c4 = idx & 15;
            float4 v = *(const float4*)&g_v[(size_t)(b * SEQ + k0 + r) * EMB + h * HDIM + c4 * 4];
            Vs[r][c4 * 4 + 0] = to_tf32(v.x);
            Vs[r][c4 * 4 + 1] = to_tf32(v.y);
            Vs[r][c4 * 4 + 2] = to_tf32(v.z);
            Vs[r][c4 * 4 + 3] = to_tf32(v.w);
        }
        __syncthreads();

        #pragma unroll
        for (int kk = 0; kk < 4; kk++) {
            const int kb = kk * 8;
            uint32_t a[2][4], bb[4][2];
            #pragma unroll
            for (int mi = 0; mi < 2; mi++) {
                int row = wm + mi * 16;
                a[mi][0] = __float_as_uint(Ps[row + g][kb + t]);
                a[mi][1] = __float_as_uint(Ps[row + 8 + g][kb + t]);
                a[mi][2] = __float_as_uint(Ps[row + g][kb + 4 + t]);
                a[mi][3] = __float_as_uint(Ps[row + 8 + g][kb + 4 + t]);
            }
            #pragma unroll
            for (int ni = 0; ni < 4; ni++) {
                int col = wn + ni * 8;   // n index
                bb[ni][0] = __float_as_uint(Vs[kb + t][col + g]);
                bb[ni][1] = __float_as_uint(Vs[kb + 4 + t][col + g]);
            }
            #pragma unroll
            for (int mi = 0; mi < 2; mi++)
                #pragma unroll
                for (int ni = 0; ni < 4; ni++)
                    mma_tf32(acc[mi][ni], a[mi][0], a[mi][1], a[mi][2], a[mi][3],
                             bb[ni][0], bb[ni][1]);
        }
        __syncthreads();
    }

    #pragma unroll
    for (int mi = 0; mi < 2; mi++) {
        #pragma unroll
        for (int ni = 0; ni < 4; ni++) {
            int m = m0 + wm + mi * 16 + g;
            int n = wn + ni * 8 + t * 2;
            g_att[(size_t)(b * SEQ + m) * EMB + h * HDIM + n]           = acc[mi][ni][0];
            g_att[(size_t)(b * SEQ + m) * EMB + h * HDIM + n + 1]       = acc[mi][ni][1];
            g_att[(size_t)(b * SEQ + m + 8) * EMB + h * HDIM + n]       = acc[mi][ni][2];
            g_att[(size_t)(b * SEQ + m + 8) * EMB + h * HDIM + n + 1]   = acc[mi][ni][3];
        }
    }
}

// ---------------------------------------------------------------------------
// launch
// ---------------------------------------------------------------------------
extern "C" void kernel_launch(void* const* d_in, const int* in_sizes, int n_in,
                              void* d_out, int out_size) {
    (void)in_sizes; (void)n_in; (void)out_size;

    const float* hs = (const float*)d_in[0];
    const float* Wq = (const float*)d_in[1];
    const float* bq = (const float*)d_in[2];
    const float* Wk = (const float*)d_in[3];
    const float* bk = (const float*)d_in[4];
    const float* Wv = (const float*)d_in[5];
    const float* bv = (const float*)d_in[6];
    const float* Wo = (const float*)d_in[7];
    const float* bo = (const float*)d_in[8];

    float* out      = (float*)d_out;
    float* attn_out = out;                          // [4,2048,768]
    float* wbuf     = out + (size_t)MTOK * EMB;     // [4,12,2048,2048]

    float* dq, * dk, * dv, * datt;
    cudaGetSymbolAddress((void**)&dq,   g_q);
    cudaGetSymbolAddress((void**)&dk,   g_k);
    cudaGetSymbolAddress((void**)&dv,   g_v);
    cudaGetSymbolAddress((void**)&datt, g_att);

    dim3 gproj(EMB / 64, MTOK / 128);               // (12, 64)

    gemm_xwT_tc<<<gproj, 256>>>(hs, Wq, bq, dq, MTOK, EMB, EMB);
    gemm_xwT_tc<<<gproj, 256>>>(hs, Wk, bk, dk, MTOK, EMB, EMB);
    gemm_xwT_tc<<<gproj, 256>>>(hs, Wv, bv, dv, MTOK, EMB, EMB);

    scores_tc<<<dim3(SEQ / 64, SEQ / 128, BATCH * HEADS), 256>>>(wbuf);

    softmax_kernel<<<BATCH * HEADS * SEQ, 256>>>(wbuf);

    pv_tc<<<dim3(1, SEQ / 128, BATCH * HEADS), 256>>>(wbuf);

    gemm_xwT_tc<<<gproj, 256>>>(datt, Wo, bo, attn_out, MTOK, EMB, EMB);
}